// round 2
// baseline (speedup 1.0000x reference)
#include <cuda_runtime.h>
#include <math.h>

#define Bn 128
#define Cn 48
#define Hn 64
#define Wn 64
#define Pn 32
#define OUT_ELEMS (Bn*Cn*Hn*Wn)

// Scratch (no allocations allowed)
__device__ unsigned long long g_M2[Cn*Cn];   // M duplicated: (m,m) packed f32x2
__device__ float4 g_Spart[1024];             // per-block score partials, bid=((b*2+g)*4+q)

#define FMA2(acc, mm, vv) asm("fma.rn.f32x2 %0, %1, %2, %0;" : "+l"(acc) : "l"(mm), "l"(vv))

// ---------------------------------------------------------------------------
// Kernel A: M[c][c2] = sum_o (Wq1[o,c]Wk1[o,c2] + ... ) / sqrt(C*p*p), duplicated
// ---------------------------------------------------------------------------
__global__ void prep_kernel(const float* __restrict__ Wq1, const float* __restrict__ Wq2,
                            const float* __restrict__ Wq3, const float* __restrict__ Wk1,
                            const float* __restrict__ Wk2, const float* __restrict__ Wk3) {
    int idx = blockIdx.x * blockDim.x + threadIdx.x;
    if (idx >= Cn*Cn) return;
    int c = idx / Cn, c2 = idx % Cn;
    float s = 0.f;
    for (int o = 0; o < Cn; ++o) {
        s += Wq1[o*Cn+c]*Wk1[o*Cn+c2]
           + Wq2[o*Cn+c]*Wk2[o*Cn+c2]
           + Wq3[o*Cn+c]*Wk3[o*Cn+c2];
    }
    s *= (1.0f / sqrtf((float)(Cn*Pn*Pn)));
    ((float2*)g_M2)[idx] = make_float2(s, s);
}

// ---------------------------------------------------------------------------
// Kernel B: scores. 1024 blocks x 128 threads. bid = ((b*2+g)*4+q).
// Thread = one masked pixel-pair (top row y, bottom row y+32, column parity g).
// Packed f32x2 matvec: rtb = (M v_t, M v_b), then 4 scalar dots.
// ---------------------------------------------------------------------------
__global__ __launch_bounds__(128, 4) void score_kernel(const float* __restrict__ x) {
    __shared__ unsigned long long sM2[Cn*Cn];   // 18432 B
    __shared__ float4 sred[4];

    int bid = blockIdx.x;
    int q = bid & 3;
    int g = (bid >> 2) & 1;
    int b = bid >> 3;
    int tid = threadIdx.x;

    #pragma unroll
    for (int i = tid; i < Cn*Cn; i += 128) sM2[i] = g_M2[i];

    int i_loc = tid >> 4;              // 0..7
    int jj    = tid & 15;              // 0..15
    int yt = q*8 + i_loc;
    int yb = 32 + yt;
    int colf2 = g*16 + jj;             // float2 column; take component g
    const float2* xb = (const float2*)(x + (size_t)b * Cn * Hn * Wn);

    unsigned long long v[Cn];          // packed (vt, vb) per channel
    if (g == 0) {
        #pragma unroll
        for (int c = 0; c < Cn; ++c) {
            float2 a  = xb[((size_t)c*Hn + yt)*32 + colf2];
            float2 bb = xb[((size_t)c*Hn + yb)*32 + colf2];
            asm("mov.b64 %0, {%1,%2};" : "=l"(v[c]) : "f"(a.x), "f"(bb.x));
        }
    } else {
        #pragma unroll
        for (int c = 0; c < Cn; ++c) {
            float2 a  = xb[((size_t)c*Hn + yt)*32 + colf2];
            float2 bb = xb[((size_t)c*Hn + yb)*32 + colf2];
            asm("mov.b64 %0, {%1,%2};" : "=l"(v[c]) : "f"(a.y), "f"(bb.y));
        }
    }
    __syncthreads();

    float p00=0.f, p01=0.f, p10=0.f, p11=0.f;
    #pragma unroll
    for (int c = 0; c < Cn; ++c) {
        unsigned long long acc = 0ULL;
        #pragma unroll
        for (int c2 = 0; c2 < Cn; ++c2) {
            FMA2(acc, sM2[c*Cn + c2], v[c2]);   // LDS.64 broadcast + FFMA2
        }
        float rt, rb;
        asm("mov.b64 {%0,%1}, %2;" : "=f"(rt), "=f"(rb) : "l"(acc));
        float vt, vb;
        asm("mov.b64 {%0,%1}, %2;" : "=f"(vt), "=f"(vb) : "l"(v[c]));
        p00 = fmaf(vt, rt, p00);  p01 = fmaf(vt, rb, p01);
        p10 = fmaf(vb, rt, p10);  p11 = fmaf(vb, rb, p11);
    }

    // deterministic reduction (no atomics)
    #pragma unroll
    for (int off = 16; off; off >>= 1) {
        p00 += __shfl_xor_sync(0xffffffffu, p00, off);
        p01 += __shfl_xor_sync(0xffffffffu, p01, off);
        p10 += __shfl_xor_sync(0xffffffffu, p10, off);
        p11 += __shfl_xor_sync(0xffffffffu, p11, off);
    }
    int wid = tid >> 5;
    if ((tid & 31) == 0) sred[wid] = make_float4(p00, p01, p10, p11);
    __syncthreads();
    if (tid == 0) {
        float4 s = sred[0];
        #pragma unroll
        for (int w = 1; w < 4; ++w) {
            float4 t = sred[w];
            s.x += t.x; s.y += t.y; s.z += t.z; s.w += t.w;
        }
        g_Spart[bid] = s;
    }
}

// ---------------------------------------------------------------------------
// Kernel C: output assembly with fused attn (softmax coeffs + logdet).
// Block = (b, c, half-of-y/x space); threads 0/1 compute the two groups'
// coefficients from g_Spart; first block of each b writes logdet.
// Evict-first stores (__stcs) keep x resident in L2.
// ---------------------------------------------------------------------------
__global__ __launch_bounds__(256) void out_kernel(const float* __restrict__ x,
                                                  const float* __restrict__ logdet_in,
                                                  const float* __restrict__ off1p,
                                                  const float* __restrict__ off2p,
                                                  const float* __restrict__ off3p,
                                                  float* __restrict__ out, int out_size) {
    __shared__ float sc[2][4];
    __shared__ float sld[2];

    int tid = threadIdx.x;
    int blk = blockIdx.x;
    int r = blk >> 1;              // r = b*48 + c (constant per block)
    int b = r / Cn;
    int c = r % Cn;

    if (tid < 2) {
        int g = tid;
        const float off  = off1p[0];
        const float off2 = off2p[0];
        const float off3 = off3p[0];
        float4 s = g_Spart[(b*2+g)*4 + 0];
        #pragma unroll
        for (int qq = 1; qq < 4; ++qq) {
            float4 t = g_Spart[(b*2+g)*4 + qq];
            s.x += t.x; s.y += t.y; s.z += t.z; s.w += t.w;
        }
        float stt = s.x + off3, stb = s.y + off3;
        float sbt = s.z + off3, sbb = s.w + off3;
        float z = off3;

        float mx  = fmaxf(fmaxf(stt, stb), z);
        float e0  = expf(stt-mx), e1 = expf(stb-mx), ez = expf(z-mx);
        float inv = 1.f / (e0 + e1 + 2.f*ez);
        float a_tt = e0*inv + off2 + off;
        float a_tb = e1*inv + off2;

        mx  = fmaxf(fmaxf(sbt, sbb), z);
        e0  = expf(sbt-mx); e1 = expf(sbb-mx); ez = expf(z-mx);
        inv = 1.f / (e0 + e1 + 2.f*ez);
        float a_bt = e0*inv + off2;
        float a_bb = e1*inv + off2 + off;

        sc[g][0]=a_tt; sc[g][1]=a_tb; sc[g][2]=a_bt; sc[g][3]=a_bb;
        float det = a_tt*a_bb - a_tb*a_bt;
        sld[g] = logf(fabsf(det)) * (float)(Pn*(Pn/2)*Cn);
    }
    __syncthreads();

    if (c == 0 && (blk & 1) == 0 && tid == 0) {
        if (OUT_ELEMS + b < out_size)
            out[OUT_ELEMS + b] = logdet_in[b] + sld[0] + sld[1];
    }

    int t  = blk * 256 + tid;
    int x4 = t & 15;
    int y  = (t >> 4) & 31;
    int g  = x4 >> 3;

    float a_tt = sc[g][0], a_tb = sc[g][1], a_bt = sc[g][2], a_bb = sc[g][3];

    size_t base = (((size_t)b*Cn + c)*Hn + y)*Wn + x4*4;
    float4 xt = *(const float4*)(x + base);
    float4 xb = *(const float4*)(x + base + 32*Wn);
    float4 ot, ob;
    if (g == 0) {  // pass-through at even lane (x,z)
        ot.x = xt.x;                    ob.x = xb.x;
        ot.y = a_tt*xt.y + a_tb*xb.y;   ob.y = a_bt*xt.y + a_bb*xb.y;
        ot.z = xt.z;                    ob.z = xb.z;
        ot.w = a_tt*xt.w + a_tb*xb.w;   ob.w = a_bt*xt.w + a_bb*xb.w;
    } else {       // pass-through at odd lane (y,w)
        ot.x = a_tt*xt.x + a_tb*xb.x;   ob.x = a_bt*xt.x + a_bb*xb.x;
        ot.y = xt.y;                    ob.y = xb.y;
        ot.z = a_tt*xt.z + a_tb*xb.z;   ob.z = a_bt*xt.z + a_bb*xb.z;
        ot.w = xt.w;                    ob.w = xb.w;
    }
    __stcs((float4*)(out + base), ot);
    __stcs((float4*)(out + base + 32*Wn), ob);
}

// ---------------------------------------------------------------------------
extern "C" void kernel_launch(void* const* d_in, const int* in_sizes, int n_in,
                              void* d_out, int out_size) {
    const float* x      = (const float*)d_in[0];
    const float* logdet = (const float*)d_in[1];
    const float* Wq1    = (const float*)d_in[2];
    const float* Wq2    = (const float*)d_in[3];
    const float* Wq3    = (const float*)d_in[4];
    const float* Wk1    = (const float*)d_in[5];
    const float* Wk2    = (const float*)d_in[6];
    const float* Wk3    = (const float*)d_in[7];
    const float* off1   = (const float*)d_in[8];
    const float* off2   = (const float*)d_in[9];
    const float* off3   = (const float*)d_in[10];
    float* out = (float*)d_out;

    prep_kernel<<<9, 256>>>(Wq1, Wq2, Wq3, Wk1, Wk2, Wk3);
    score_kernel<<<1024, 128>>>(x);
    out_kernel<<<12288, 256>>>(x, logdet, off1, off2, off3, out, out_size);
}

// round 3
// speedup vs baseline: 1.1173x; 1.1173x over previous
#include <cuda_runtime.h>
#include <math.h>

#define Bn 128
#define Cn 48
#define Hn 64
#define Wn 64
#define Pn 32
#define OUT_ELEMS (Bn*Cn*Hn*Wn)

// Scratch (no allocations allowed)
__device__ unsigned long long g_M2[Cn*Cn];   // M duplicated: (m,m) packed f32x2
__device__ float4 g_Spart[1024];             // per-block score partials, bid=((b*2+g)*4+q)

#define FMA2(acc, mm, vv) asm("fma.rn.f32x2 %0, %1, %2, %0;" : "+l"(acc) : "l"(mm), "l"(vv))

// ---------------------------------------------------------------------------
// Kernel A: warp-per-output. M[c][c2] = sum_o (Wq1[o,c]Wk1[o,c2]+...)/scale.
// 2304 outputs, one warp each: lane l sums o in {l, l+32}, shfl-reduce.
// ---------------------------------------------------------------------------
__global__ __launch_bounds__(256) void prep_kernel(
        const float* __restrict__ Wq1, const float* __restrict__ Wq2,
        const float* __restrict__ Wq3, const float* __restrict__ Wk1,
        const float* __restrict__ Wk2, const float* __restrict__ Wk3) {
    int w    = (blockIdx.x * 256 + threadIdx.x) >> 5;   // output index
    int lane = threadIdx.x & 31;
    if (w >= Cn*Cn) return;
    int c = w / Cn, c2 = w % Cn;

    float s = 0.f;
    #pragma unroll
    for (int o = lane; o < Cn; o += 32) {
        s += Wq1[o*Cn+c]*Wk1[o*Cn+c2]
           + Wq2[o*Cn+c]*Wk2[o*Cn+c2]
           + Wq3[o*Cn+c]*Wk3[o*Cn+c2];
    }
    #pragma unroll
    for (int off = 16; off; off >>= 1)
        s += __shfl_xor_sync(0xffffffffu, s, off);

    if (lane == 0) {
        s *= (1.0f / sqrtf((float)(Cn*Pn*Pn)));
        ((float2*)g_M2)[w] = make_float2(s, s);
    }
}

// ---------------------------------------------------------------------------
// Kernel B: scores. 1024 blocks x 128 threads. bid = ((b*2+g)*4+q).
// Thread = one masked pixel-pair (top row y, bottom row y+32, parity g).
// Packed f32x2 matvec with dual accumulators; launch_bounds(128,3) -> no spill.
// ---------------------------------------------------------------------------
__global__ __launch_bounds__(128, 3) void score_kernel(const float* __restrict__ x) {
    __shared__ unsigned long long sM2[Cn*Cn];   // 18432 B
    __shared__ float4 sred[4];

    int bid = blockIdx.x;
    int q = bid & 3;
    int g = (bid >> 2) & 1;
    int b = bid >> 3;
    int tid = threadIdx.x;

    #pragma unroll
    for (int i = tid; i < Cn*Cn; i += 128) sM2[i] = g_M2[i];

    int i_loc = tid >> 4;              // 0..7
    int jj    = tid & 15;              // 0..15
    int yt = q*8 + i_loc;
    int yb = 32 + yt;
    int colf2 = g*16 + jj;             // float2 column; take component g
    const float2* xb = (const float2*)(x + (size_t)b * Cn * Hn * Wn);

    unsigned long long v[Cn];          // packed (vt, vb) per channel
    if (g == 0) {
        #pragma unroll
        for (int c = 0; c < Cn; ++c) {
            float2 a  = xb[((size_t)c*Hn + yt)*32 + colf2];
            float2 bb = xb[((size_t)c*Hn + yb)*32 + colf2];
            asm("mov.b64 %0, {%1,%2};" : "=l"(v[c]) : "f"(a.x), "f"(bb.x));
        }
    } else {
        #pragma unroll
        for (int c = 0; c < Cn; ++c) {
            float2 a  = xb[((size_t)c*Hn + yt)*32 + colf2];
            float2 bb = xb[((size_t)c*Hn + yb)*32 + colf2];
            asm("mov.b64 %0, {%1,%2};" : "=l"(v[c]) : "f"(a.y), "f"(bb.y));
        }
    }
    __syncthreads();

    float p00=0.f, p01=0.f, p10=0.f, p11=0.f;
    #pragma unroll
    for (int c = 0; c < Cn; ++c) {
        unsigned long long acc0 = 0ULL, acc1 = 0ULL;
        #pragma unroll
        for (int c2 = 0; c2 < Cn; c2 += 2) {
            FMA2(acc0, sM2[c*Cn + c2],     v[c2]);
            FMA2(acc1, sM2[c*Cn + c2 + 1], v[c2 + 1]);
        }
        float rt0, rb0, rt1, rb1;
        asm("mov.b64 {%0,%1}, %2;" : "=f"(rt0), "=f"(rb0) : "l"(acc0));
        asm("mov.b64 {%0,%1}, %2;" : "=f"(rt1), "=f"(rb1) : "l"(acc1));
        float rt = rt0 + rt1, rb = rb0 + rb1;
        float vt, vb;
        asm("mov.b64 {%0,%1}, %2;" : "=f"(vt), "=f"(vb) : "l"(v[c]));
        p00 = fmaf(vt, rt, p00);  p01 = fmaf(vt, rb, p01);
        p10 = fmaf(vb, rt, p10);  p11 = fmaf(vb, rb, p11);
    }

    // deterministic reduction (no atomics)
    #pragma unroll
    for (int off = 16; off; off >>= 1) {
        p00 += __shfl_xor_sync(0xffffffffu, p00, off);
        p01 += __shfl_xor_sync(0xffffffffu, p01, off);
        p10 += __shfl_xor_sync(0xffffffffu, p10, off);
        p11 += __shfl_xor_sync(0xffffffffu, p11, off);
    }
    int wid = tid >> 5;
    if ((tid & 31) == 0) sred[wid] = make_float4(p00, p01, p10, p11);
    __syncthreads();
    if (tid == 0) {
        float4 s = sred[0];
        #pragma unroll
        for (int w = 1; w < 4; ++w) {
            float4 t = sred[w];
            s.x += t.x; s.y += t.y; s.z += t.z; s.w += t.w;
        }
        g_Spart[bid] = s;
    }
}

// ---------------------------------------------------------------------------
// Kernel C: output assembly with fused attn. Global x loads are issued BEFORE
// the coeff computation / syncthreads so the softmax head is hidden.
// ---------------------------------------------------------------------------
__global__ __launch_bounds__(256) void out_kernel(const float* __restrict__ x,
                                                  const float* __restrict__ logdet_in,
                                                  const float* __restrict__ off1p,
                                                  const float* __restrict__ off2p,
                                                  const float* __restrict__ off3p,
                                                  float* __restrict__ out, int out_size) {
    __shared__ float sc[2][4];
    __shared__ float sld[2];

    int tid = threadIdx.x;
    int blk = blockIdx.x;
    int r = blk >> 1;              // r = b*48 + c (constant per block)
    int b = r / Cn;
    int c = r % Cn;

    // issue main loads first (independent of the coeffs)
    int t  = blk * 256 + tid;
    int x4 = t & 15;
    int y  = (t >> 4) & 31;
    int g  = x4 >> 3;
    size_t base = (((size_t)b*Cn + c)*Hn + y)*Wn + x4*4;
    float4 xt = *(const float4*)(x + base);
    float4 xb = *(const float4*)(x + base + 32*Wn);

    if (tid < 2) {
        int gg = tid;
        const float off  = off1p[0];
        const float off2 = off2p[0];
        const float off3 = off3p[0];
        float4 s = g_Spart[(b*2+gg)*4 + 0];
        #pragma unroll
        for (int qq = 1; qq < 4; ++qq) {
            float4 tt = g_Spart[(b*2+gg)*4 + qq];
            s.x += tt.x; s.y += tt.y; s.z += tt.z; s.w += tt.w;
        }
        float stt = s.x + off3, stb = s.y + off3;
        float sbt = s.z + off3, sbb = s.w + off3;
        float z = off3;

        float mx  = fmaxf(fmaxf(stt, stb), z);
        float e0  = expf(stt-mx), e1 = expf(stb-mx), ez = expf(z-mx);
        float inv = 1.f / (e0 + e1 + 2.f*ez);
        float a_tt = e0*inv + off2 + off;
        float a_tb = e1*inv + off2;

        mx  = fmaxf(fmaxf(sbt, sbb), z);
        e0  = expf(sbt-mx); e1 = expf(sbb-mx); ez = expf(z-mx);
        inv = 1.f / (e0 + e1 + 2.f*ez);
        float a_bt = e0*inv + off2;
        float a_bb = e1*inv + off2 + off;

        sc[gg][0]=a_tt; sc[gg][1]=a_tb; sc[gg][2]=a_bt; sc[gg][3]=a_bb;
        float det = a_tt*a_bb - a_tb*a_bt;
        sld[gg] = logf(fabsf(det)) * (float)(Pn*(Pn/2)*Cn);
    }
    __syncthreads();

    if (c == 0 && (blk & 1) == 0 && tid == 0) {
        if (OUT_ELEMS + b < out_size)
            out[OUT_ELEMS + b] = logdet_in[b] + sld[0] + sld[1];
    }

    float a_tt = sc[g][0], a_tb = sc[g][1], a_bt = sc[g][2], a_bb = sc[g][3];

    float4 ot, ob;
    if (g == 0) {  // pass-through at even lane (x,z)
        ot.x = xt.x;                    ob.x = xb.x;
        ot.y = a_tt*xt.y + a_tb*xb.y;   ob.y = a_bt*xt.y + a_bb*xb.y;
        ot.z = xt.z;                    ob.z = xb.z;
        ot.w = a_tt*xt.w + a_tb*xb.w;   ob.w = a_bt*xt.w + a_bb*xb.w;
    } else {       // pass-through at odd lane (y,w)
        ot.x = a_tt*xt.x + a_tb*xb.x;   ob.x = a_bt*xt.x + a_bb*xb.x;
        ot.y = xt.y;                    ob.y = xb.y;
        ot.z = a_tt*xt.z + a_tb*xb.z;   ob.z = a_bt*xt.z + a_bb*xb.z;
        ot.w = xt.w;                    ob.w = xb.w;
    }
    __stcs((float4*)(out + base), ot);
    __stcs((float4*)(out + base + 32*Wn), ob);
}

// ---------------------------------------------------------------------------
extern "C" void kernel_launch(void* const* d_in, const int* in_sizes, int n_in,
                              void* d_out, int out_size) {
    const float* x      = (const float*)d_in[0];
    const float* logdet = (const float*)d_in[1];
    const float* Wq1    = (const float*)d_in[2];
    const float* Wq2    = (const float*)d_in[3];
    const float* Wq3    = (const float*)d_in[4];
    const float* Wk1    = (const float*)d_in[5];
    const float* Wk2    = (const float*)d_in[6];
    const float* Wk3    = (const float*)d_in[7];
    const float* off1   = (const float*)d_in[8];
    const float* off2   = (const float*)d_in[9];
    const float* off3   = (const float*)d_in[10];
    float* out = (float*)d_out;

    prep_kernel<<<288, 256>>>(Wq1, Wq2, Wq3, Wk1, Wk2, Wk3);
    score_kernel<<<1024, 128>>>(x);
    out_kernel<<<12288, 256>>>(x, logdet, off1, off2, off3, out, out_size);
}